// round 5
// baseline (speedup 1.0000x reference)
#include <cuda_runtime.h>

#define NCTA  296
#define BLK   256
#define BTOT  2048
#define LLEN  512
#define FDIM  64
#define GDIM  256
#define SGMAX 7

__device__ __forceinline__ unsigned long long ffma2(unsigned long long a,
                                                    unsigned long long b,
                                                    unsigned long long c) {
    unsigned long long d;
    asm("fma.rn.f32x2 %0, %1, %2, %3;" : "=l"(d) : "l"(a), "l"(b), "l"(c));
    return d;
}
__device__ __forceinline__ unsigned long long pack2(float lo, float hi) {
    unsigned long long r;
    asm("mov.b64 %0, {%1, %2};" : "=l"(r) : "f"(lo), "f"(hi));
    return r;
}
__device__ __forceinline__ void unpack2(unsigned long long v, float& lo, float& hi) {
    asm("mov.b64 {%0, %1}, %2;" : "=f"(lo), "=f"(hi) : "l"(v));
}
__device__ __forceinline__ float sigf(float x) {
    return __fdividef(1.0f, 1.0f + __expf(-x));
}

__global__ void __launch_bounds__(BLK, 2) rnn_lstm_kernel(
    const int*   __restrict__ s,
    const float* __restrict__ W0, const float* __restrict__ b0,
    const float* __restrict__ Wi, const float* __restrict__ Wh,
    const float* __restrict__ bh, const float* __restrict__ Wa,
    const float* __restrict__ ba,
    float* __restrict__ out)                      // REAL amp only
{
    __shared__ __align__(16) float hbuf[2][SGMAX][FDIM];
    __shared__ float2 parts[2][SGMAX][8];
    __shared__ int    toks[SGMAX][LLEN];

    const int tid  = threadIdx.x;
    const int w    = tid >> 5;
    const int lane = tid & 31;
    const int m    = lane >> 2;
    const int g    = lane & 3;                 // 0:i 1:f 2:g(tanh) 3:o
    const int u    = w + 8 * m;                // hidden unit 0..63
    const int col  = u + 64 * g;               // gate column 0..255
    const int cta  = blockIdx.x;
    const int SG   = (BTOT - cta + NCTA - 1) / NCTA;   // 6 or 7 samples

    // ---- recurrent weights for this gate column, packed f32x2 over k ----
    unsigned long long w2[FDIM / 2];
#pragma unroll
    for (int j = 0; j < FDIM / 2; j++)
        w2[j] = pack2(Wh[(2 * j) * GDIM + col], Wh[(2 * j + 1) * GDIM + col]);

    // ---- input table: xw[tok] = (W0[tok,:] + b0) @ Wi[:,col] + bh[col] ----
    float xw0 = bh[col], xw1 = xw0;
    for (int k = 0; k < FDIM; k++) {
        float wik = Wi[k * GDIM + col];
        float bk  = b0[k];
        xw0 = fmaf(W0[k]        + bk, wik, xw0);
        xw1 = fmaf(W0[FDIM + k] + bk, wik, xw1);
    }

    const float wa0 = Wa[2 * u], wa1 = Wa[2 * u + 1];
    const float ba0 = ba[0],     ba1 = ba[1];

    // ---- stage tokens; zero h ----
    for (int idx = tid; idx < SG * LLEN; idx += BLK) {
        int si = idx >> 9;
        int l  = idx & (LLEN - 1);
        toks[si][l] = s[(cta + si * NCTA) * LLEN + l];
    }
    for (int idx = tid; idx < SGMAX * FDIM; idx += BLK)
        (&hbuf[0][0][0])[idx] = 0.0f;

    float cst[SGMAX];
#pragma unroll
    for (int si = 0; si < SGMAX; si++) cst[si] = 0.0f;

    __syncthreads();

    float amp = 0.0f;

    for (int t = 0; t < LLEN; t++) {
        const int buf = t & 1;

#pragma unroll
        for (int si = 0; si < SGMAX; si++) {
            if (si >= SG) break;
            const int tok_in = (t == 0) ? 0 : toks[si][t - 1];
            unsigned long long acc = pack2(tok_in ? xw1 : xw0, 0.0f);
            const ulonglong2* hp =
                reinterpret_cast<const ulonglong2*>(&hbuf[buf][si][0]);
#pragma unroll
            for (int q = 0; q < 16; q++) {          // 64-term dot, f32x2 pairs
                ulonglong2 hv = hp[q];               // LDS.128 broadcast
                acc = ffma2(hv.x, w2[2 * q],     acc);
                acc = ffma2(hv.y, w2[2 * q + 1], acc);
            }
            float alo, ahi;
            unpack2(acc, alo, ahi);
            float a = alo + ahi;

            // g==2 -> tanh(a) ; else sigmoid(a)
            float r = sigf((g == 2) ? 2.0f * a : a);
            float v = (g == 2) ? fmaf(2.0f, r, -1.0f) : r;

            const int base = lane & ~3;
            float iv = __shfl_sync(0xffffffffu, v, base + 0);
            float fv = __shfl_sync(0xffffffffu, v, base + 1);
            float gv = __shfl_sync(0xffffffffu, v, base + 2);
            float ov = __shfl_sync(0xffffffffu, v, base + 3);

            float cn = fmaf(fv, cst[si], iv * gv);
            cst[si]  = cn;
            float tc = fmaf(2.0f, sigf(2.0f * cn), -1.0f);   // tanh(cn)
            float hn = ov * tc;

            if (g == 0) hbuf[buf ^ 1][si][u] = hn;

            // logit partials: only g==0 lanes contribute (one per unit u)
            float p0 = (g == 0) ? hn * wa0 : 0.0f;
            float p1 = (g == 0) ? hn * wa1 : 0.0f;
#pragma unroll
            for (int off = 4; off < 32; off <<= 1) {
                p0 += __shfl_xor_sync(0xffffffffu, p0, off);
                p1 += __shfl_xor_sync(0xffffffffu, p1, off);
            }
            if (lane == 0) parts[buf][si][w] = make_float2(p0, p1);
        }

        __syncthreads();

        // per-step logit reduce + log-softmax accumulate (thread si = sample si)
        if (tid < SG) {
            float z0 = ba0, z1 = ba1;
#pragma unroll
            for (int ww = 0; ww < 8; ww++) {
                float2 p = parts[buf][tid][ww];
                z0 += p.x; z1 += p.y;
            }
            int   tok = toks[tid][t];
            float mx  = fmaxf(z0, z1);
            float lse = mx + log1pf(__expf(-fabsf(z0 - z1)));
            amp += 0.5f * ((tok ? z1 : z0) - lse);
        }
        // parts[buf] safely reused at t+2: reader passes barrier(t+1) first.
    }

    if (tid < SG)
        out[cta + tid * NCTA] = amp;    // real part only (float32[2048])
}

extern "C" void kernel_launch(void* const* d_in, const int* in_sizes, int n_in,
                              void* d_out, int out_size) {
    (void)in_sizes; (void)n_in; (void)out_size;
    rnn_lstm_kernel<<<NCTA, BLK>>>(
        (const int*)  d_in[0],            // s
        (const float*)d_in[1],            // W0
        (const float*)d_in[2],            // b0
        (const float*)d_in[3],            // Wi
        (const float*)d_in[4],            // Wh
        (const float*)d_in[5],            // bh
        (const float*)d_in[6],            // Wa
        (const float*)d_in[7],            // ba
        (float*)d_out);                   // amp (real) only
}

// round 6
// speedup vs baseline: 1.0137x; 1.0137x over previous
#include <cuda_runtime.h>

#define NCTA  296
#define BLK   256
#define BTOT  2048
#define LLEN  512
#define FDIM  64
#define GDIM  256
#define SGMAX 7

__device__ __forceinline__ unsigned long long ffma2(unsigned long long a,
                                                    unsigned long long b,
                                                    unsigned long long c) {
    unsigned long long d;
    asm("fma.rn.f32x2 %0, %1, %2, %3;" : "=l"(d) : "l"(a), "l"(b), "l"(c));
    return d;
}
__device__ __forceinline__ unsigned long long add2(unsigned long long a,
                                                   unsigned long long b) {
    unsigned long long d;
    asm("add.rn.f32x2 %0, %1, %2;" : "=l"(d) : "l"(a), "l"(b));
    return d;
}
__device__ __forceinline__ unsigned long long pack2(float lo, float hi) {
    unsigned long long r;
    asm("mov.b64 %0, {%1, %2};" : "=l"(r) : "f"(lo), "f"(hi));
    return r;
}
__device__ __forceinline__ void unpack2(unsigned long long v, float& lo, float& hi) {
    asm("mov.b64 {%0, %1}, %2;" : "=f"(lo), "=f"(hi) : "l"(v));
}
__device__ __forceinline__ float tanh_ap(float x) {
    float y;
    asm("tanh.approx.f32 %0, %1;" : "=f"(y) : "f"(x));
    return y;
}

__global__ void __launch_bounds__(BLK, 2) rnn_lstm_kernel(
    const int*   __restrict__ s,
    const float* __restrict__ W0, const float* __restrict__ b0,
    const float* __restrict__ Wi, const float* __restrict__ Wh,
    const float* __restrict__ bh, const float* __restrict__ Wa,
    const float* __restrict__ ba,
    float* __restrict__ out)
{
    __shared__ __align__(16) float hbuf[2][SGMAX][FDIM];
    __shared__ __align__(16) float parts[2][SGMAX][2][8];   // [buf][si][z0/z1][warp]
    __shared__ int toks[SGMAX][LLEN];

    const int tid  = threadIdx.x;
    const int w    = tid >> 5;
    const int lane = tid & 31;
    const int m    = lane >> 2;
    const int g    = lane & 3;                 // 0:i 1:f 2:g(tanh) 3:o
    const int u    = w + 8 * m;                // hidden unit 0..63
    const int col  = u + 64 * g;               // gate column 0..255
    const int cta  = blockIdx.x;

    // ---- recurrent weights for this gate column, packed f32x2 over k ----
    unsigned long long w2[FDIM / 2];
#pragma unroll
    for (int j = 0; j < FDIM / 2; j++)
        w2[j] = pack2(Wh[(2 * j) * GDIM + col], Wh[(2 * j + 1) * GDIM + col]);

    // ---- input table: xw[tok] = (W0[tok,:] + b0) @ Wi[:,col] + bh[col] ----
    float xw0 = bh[col], xw1 = xw0;
    for (int k = 0; k < FDIM; k++) {
        float wik = Wi[k * GDIM + col];
        float bk  = b0[k];
        xw0 = fmaf(W0[k]        + bk, wik, xw0);
        xw1 = fmaf(W0[FDIM + k] + bk, wik, xw1);
    }

    const float wa0 = Wa[2 * u], wa1 = Wa[2 * u + 1];
    const float ba0 = ba[0],     ba1 = ba[1];

    // ---- stage tokens (clamped for uniform-7 processing); zero h ----
    for (int idx = tid; idx < SGMAX * LLEN; idx += BLK) {
        int si = idx >> 9;
        int l  = idx & (LLEN - 1);
        int b  = cta + si * NCTA;
        if (b >= BTOT) b = BTOT - 1;           // clamp: dummy sample, never output
        toks[si][l] = s[b * LLEN + l];
    }
    for (int idx = tid; idx < SGMAX * FDIM; idx += BLK)
        (&hbuf[0][0][0])[idx] = 0.0f;

    float cst[SGMAX];
#pragma unroll
    for (int si = 0; si < SGMAX; si++) cst[si] = 0.0f;

    __syncthreads();

    float amp = 0.0f;   // valid in lane 0 of warp si (sample cta + si*NCTA)

    for (int t = 0; t < LLEN; t++) {
        const int buf = t & 1;

#pragma unroll
        for (int si = 0; si < SGMAX; si++) {
            const int tok_in = (t == 0) ? 0 : toks[si][t - 1];

            // ---- 64-term dot: 4 independent f32x2 chains of length 8 ----
            unsigned long long a0 = pack2(tok_in ? xw1 : xw0, 0.0f);
            unsigned long long a1 = pack2(0.0f, 0.0f);
            unsigned long long a2 = a1, a3 = a1;
            const ulonglong2* hp =
                reinterpret_cast<const ulonglong2*>(&hbuf[buf][si][0]);
#pragma unroll
            for (int q = 0; q < 16; q += 2) {
                ulonglong2 hA = hp[q];                 // LDS.128 broadcast
                ulonglong2 hB = hp[q + 1];
                a0 = ffma2(hA.x, w2[2 * q + 0], a0);
                a1 = ffma2(hA.y, w2[2 * q + 1], a1);
                a2 = ffma2(hB.x, w2[2 * q + 2], a2);
                a3 = ffma2(hB.y, w2[2 * q + 3], a3);
            }
            unsigned long long acc = add2(add2(a0, a1), add2(a2, a3));
            float alo, ahi;
            unpack2(acc, alo, ahi);
            float a = alo + ahi;

            // ---- activation: 1 MUFU.TANH for every gate ----
            // g==2: tanh(a);  else: sigmoid(a) = 0.5 + 0.5*tanh(a/2)
            float arg = (g == 2) ? a : 0.5f * a;
            float th  = tanh_ap(arg);
            float v   = (g == 2) ? th : fmaf(0.5f, th, 0.5f);

            const int base = lane & ~3;
            float iv = __shfl_sync(0xffffffffu, v, base + 0);
            float fv = __shfl_sync(0xffffffffu, v, base + 1);
            float gv = __shfl_sync(0xffffffffu, v, base + 2);
            float ov = __shfl_sync(0xffffffffu, v, base + 3);

            float cn = fmaf(fv, cst[si], iv * gv);
            cst[si]  = cn;
            float hn = ov * tanh_ap(cn);

            if (g == 0) hbuf[buf ^ 1][si][u] = hn;

            // ---- logit partials: lane g==0 carries p0, g==1 carries p1 ----
            float pr = (g == 0) ? hn * wa0 : ((g == 1) ? hn * wa1 : 0.0f);
#pragma unroll
            for (int off = 4; off < 32; off <<= 1)
                pr += __shfl_xor_sync(0xffffffffu, pr, off);
            if (lane < 2) parts[buf][si][lane][w] = pr;
        }

        __syncthreads();

        // ---- phase 3: lane 0 of warp si reduces sample si ----
        if (lane == 0 && w < SGMAX) {
            const float4* p0 =
                reinterpret_cast<const float4*>(&parts[buf][w][0][0]);
            float4 q0 = p0[0], q1 = p0[1], q2 = p0[2], q3 = p0[3];
            float z0 = ba0 + q0.x + q0.y + q0.z + q0.w + q1.x + q1.y + q1.z + q1.w;
            float z1 = ba1 + q2.x + q2.y + q2.z + q2.w + q3.x + q3.y + q3.z + q3.w;
            int   tok = toks[w][t];
            float mx  = fmaxf(z0, z1);
            float lse = mx + log1pf(__expf(-fabsf(z0 - z1)));
            amp += 0.5f * ((tok ? z1 : z0) - lse);
        }
        // parts[buf] reuse at t+2 is safe: readers pass barrier(t+1) first.
    }

    if (lane == 0 && w < SGMAX) {
        int b = cta + w * NCTA;
        if (b < BTOT) out[b] = amp;
    }
}

extern "C" void kernel_launch(void* const* d_in, const int* in_sizes, int n_in,
                              void* d_out, int out_size) {
    (void)in_sizes; (void)n_in; (void)out_size;
    rnn_lstm_kernel<<<NCTA, BLK>>>(
        (const int*)  d_in[0],            // s
        (const float*)d_in[1],            // W0
        (const float*)d_in[2],            // b0
        (const float*)d_in[3],            // Wi
        (const float*)d_in[4],            // Wh
        (const float*)d_in[5],            // bh
        (const float*)d_in[6],            // Wa
        (const float*)d_in[7],            // ba
        (float*)d_out);                   // amp (real part) float32[2048]
}